// round 1
// baseline (speedup 1.0000x reference)
#include <cuda_runtime.h>
#include <cuda_bf16.h>

// Fixed problem dims (shapes are fixed for this problem instance)
#define MAX_N   100000
#define MAX_E   1600000
#define IN_DIM  128
#define HID     64

// ---------------- device scratch (no allocations allowed) ----------------
__device__ float g_t[MAX_N * HID];        // GEMM output (pre-aggregation messages)
__device__ float g_h[MAX_N * HID];        // aggregated + relu activations
__device__ float g_dinv[MAX_N];           // deg^{-1/2}
__device__ int   g_deg[MAX_N];            // degree incl. self loop
__device__ int   g_rowstart[MAX_N + 1];   // CSR row offsets (by dst)
__device__ int   g_fill[MAX_N];           // scatter cursors
__device__ int   g_srce[MAX_E];           // edge src (int32)
__device__ int   g_dste[MAX_E];           // edge dst (int32)
__device__ int   g_col[MAX_E];            // CSR column (src) sorted by dst
__device__ int   g_is64;                  // edge_index dtype flag

// ---------------- dtype detection ----------------
// Sample the first e int64 slots (safe whether the buffer holds e*2 int32 or
// e*2 int64). If the data is really int64 indices, every sampled value lies in
// [0, n). If it's int32 pairs viewed as int64, values combine two indices and
// blow past n with overwhelming probability.
__global__ void k_detect(const void* ei, int e, int n) {
    __shared__ int bad;
    if (threadIdx.x == 0) bad = 0;
    __syncthreads();
    const long long* p = (const long long*)ei;
    int samples = e < 2048 ? e : 2048;
    long long stride = e / samples; if (stride < 1) stride = 1;
    for (int i = threadIdx.x; i < samples; i += blockDim.x) {
        long long idx = (long long)i * stride;
        if (idx < e) {
            long long v = p[idx];
            if (v < 0 || v >= n) bad = 1;
        }
    }
    __syncthreads();
    if (threadIdx.x == 0) g_is64 = bad ? 0 : 1;
}

__global__ void k_convert(const void* ei, int e) {
    int i = blockIdx.x * blockDim.x + threadIdx.x;
    if (i >= e) return;
    if (g_is64) {
        const long long* p = (const long long*)ei;
        g_srce[i] = (int)p[i];
        g_dste[i] = (int)p[e + i];
    } else {
        const int* p = (const int*)ei;
        g_srce[i] = p[i];
        g_dste[i] = p[e + i];
    }
}

// ---------------- degree / norm ----------------
__global__ void k_deg_init(int n) {
    int i = blockIdx.x * blockDim.x + threadIdx.x;
    if (i < n) g_deg[i] = 1;   // self loop
}

__global__ void k_deg_count(int e) {
    int i = blockIdx.x * blockDim.x + threadIdx.x;
    if (i < e) atomicAdd(&g_deg[g_dste[i]], 1);
}

__global__ void k_dinv(int n) {
    int i = blockIdx.x * blockDim.x + threadIdx.x;
    if (i < n) g_dinv[i] = rsqrtf((float)g_deg[i]);
}

// ---------------- single-block tiled exclusive scan over (deg-1) ----------
__global__ void k_scan(int n) {
    __shared__ int sh[1024];
    __shared__ int carry_sh;
    int tid = threadIdx.x;
    if (tid == 0) carry_sh = 0;
    __syncthreads();
    int ntiles = (n + 1023) / 1024;
    for (int tile = 0; tile < ntiles; ++tile) {
        int i = tile * 1024 + tid;
        int v = (i < n) ? (g_deg[i] - 1) : 0;
        sh[tid] = v;
        __syncthreads();
        #pragma unroll
        for (int off = 1; off < 1024; off <<= 1) {
            int add = (tid >= off) ? sh[tid - off] : 0;
            __syncthreads();
            sh[tid] += add;
            __syncthreads();
        }
        int incl = sh[tid];
        int excl = incl - v;
        int carry = carry_sh;     // value from previous tile (synced)
        if (i < n) {
            g_rowstart[i] = carry + excl;
            g_fill[i]     = carry + excl;
        }
        __syncthreads();
        if (tid == 1023) carry_sh = carry + incl;
        __syncthreads();
    }
    if (tid == 0) g_rowstart[n] = carry_sh;
}

__global__ void k_scatter(int e) {
    int i = blockIdx.x * blockDim.x + threadIdx.x;
    if (i >= e) return;
    int d = g_dste[i];
    int pos = atomicAdd(&g_fill[d], 1);
    g_col[pos] = g_srce[i];
}

// ---------------- dense transform: out[n,64] = A[n,K] @ W[K,64] -----------
template <int K>
__global__ void k_gemm(const float* __restrict__ A, const float* __restrict__ W,
                       float* __restrict__ out, int n) {
    __shared__ float Ws[K * 64];
    __shared__ float As[8 * K];
    int tx = threadIdx.x;           // 0..63  (output column)
    int ty = threadIdx.y;           // 0..7   (row within tile)
    int tid = ty * 64 + tx;         // 0..511
    for (int i = tid; i < K * 64; i += 512) Ws[i] = W[i];
    int row0 = blockIdx.x * 8;
    for (int i = tid; i < 8 * K; i += 512) {
        int r = row0 + i / K;
        As[i] = (r < n) ? A[(long long)r * K + (i % K)] : 0.f;
    }
    __syncthreads();
    float acc = 0.f;
    #pragma unroll
    for (int k = 0; k < K; ++k)
        acc = fmaf(As[ty * K + k], Ws[k * 64 + tx], acc);
    int row = row0 + ty;
    if (row < n) out[(long long)row * 64 + tx] = acc;
}

// ---------------- CSR aggregation: warp per node, float2 per lane ---------
// h_out[i] = relu( b + dinv_i^2 * t[i] + sum_{s in in(i)} dinv_s*dinv_i * t[s] )
__global__ void k_agg(const float* __restrict__ t, const float* __restrict__ b,
                      float* __restrict__ hout, int n) {
    int warp = (blockIdx.x * blockDim.x + threadIdx.x) >> 5;
    int lane = threadIdx.x & 31;
    if (warp >= n) return;
    int i = warp;
    const float2* __restrict__ t2 = (const float2*)t;
    float di = g_dinv[i];
    float2 self = t2[(long long)i * 32 + lane];
    float ns = di * di;
    float ax = self.x * ns, ay = self.y * ns;
    int s0 = g_rowstart[i], s1 = g_rowstart[i + 1];
    int idx = s0;
    for (; idx + 1 < s1; idx += 2) {
        int sA = g_col[idx], sB = g_col[idx + 1];
        float nA = g_dinv[sA] * di, nB = g_dinv[sB] * di;
        float2 vA = t2[(long long)sA * 32 + lane];
        float2 vB = t2[(long long)sB * 32 + lane];
        ax = fmaf(vA.x, nA, ax); ay = fmaf(vA.y, nA, ay);
        ax = fmaf(vB.x, nB, ax); ay = fmaf(vB.y, nB, ay);
    }
    if (idx < s1) {
        int s = g_col[idx];
        float nm = g_dinv[s] * di;
        float2 v = t2[(long long)s * 32 + lane];
        ax = fmaf(v.x, nm, ax); ay = fmaf(v.y, nm, ay);
    }
    ax += b[2 * lane];
    ay += b[2 * lane + 1];
    float2 o;
    o.x = fmaxf(ax, 0.f);
    o.y = fmaxf(ay, 0.f);
    ((float2*)hout)[(long long)i * 32 + lane] = o;
}

// ---------------- MLP head: warp per node ----------------
// out = relu(h @ Wp1 + bp1) @ Wp2 + bp2
__global__ void k_mlp(const float* __restrict__ h,
                      const float* __restrict__ Wp1, const float* __restrict__ bp1,
                      const float* __restrict__ Wp2, const float* __restrict__ bp2,
                      float* __restrict__ out, int n) {
    __shared__ float W1s[64 * 32];
    __shared__ float W2s[32];
    int tid = threadIdx.x;  // 256
    for (int i = tid; i < 64 * 32; i += 256) W1s[i] = Wp1[i];
    if (tid < 32) W2s[tid] = Wp2[tid];
    __syncthreads();
    int warp = tid >> 5, lane = tid & 31;
    int node = blockIdx.x * 8 + warp;
    if (node >= n) return;
    float hlo = h[(long long)node * 64 + lane];
    float hhi = h[(long long)node * 64 + 32 + lane];
    float acc = 0.f;
    #pragma unroll
    for (int k = 0; k < 32; ++k)
        acc = fmaf(__shfl_sync(0xffffffffu, hlo, k), W1s[k * 32 + lane], acc);
    #pragma unroll
    for (int k = 0; k < 32; ++k)
        acc = fmaf(__shfl_sync(0xffffffffu, hhi, k), W1s[(k + 32) * 32 + lane], acc);
    float z = fmaxf(acc + bp1[lane], 0.f);
    float p = z * W2s[lane];
    #pragma unroll
    for (int o = 16; o > 0; o >>= 1) p += __shfl_xor_sync(0xffffffffu, p, o);
    if (lane == 0) out[node] = p + bp2[0];
}

// ---------------- launch ----------------
extern "C" void kernel_launch(void* const* d_in, const int* in_sizes, int n_in,
                              void* d_out, int out_size) {
    const float* x   = (const float*)d_in[0];
    const void*  ei  = d_in[1];
    // d_in[2] = batch (unused, all zeros)
    const float* W1  = (const float*)d_in[3];
    const float* b1  = (const float*)d_in[4];
    const float* W2  = (const float*)d_in[5];
    const float* b2  = (const float*)d_in[6];
    const float* W3  = (const float*)d_in[7];
    const float* b3  = (const float*)d_in[8];
    const float* Wp1 = (const float*)d_in[9];
    const float* bp1 = (const float*)d_in[10];
    const float* Wp2 = (const float*)d_in[11];
    const float* bp2 = (const float*)d_in[12];
    float* out = (float*)d_out;

    int n = in_sizes[0] / IN_DIM;
    int e = in_sizes[1] / 2;

    float* t = nullptr; float* h = nullptr;
    cudaGetSymbolAddress((void**)&t, g_t);
    cudaGetSymbolAddress((void**)&h, g_h);

    int nb_n  = (n + 255) / 256;
    int nb_e  = (e + 255) / 256;
    int nb_w8 = (n + 7) / 8;        // warp-per-node kernels, 8 warps/block

    // --- graph preprocessing (once per launch) ---
    k_detect<<<1, 256>>>(ei, e, n);
    k_convert<<<nb_e, 256>>>(ei, e);
    k_deg_init<<<nb_n, 256>>>(n);
    k_deg_count<<<nb_e, 256>>>(e);
    k_dinv<<<nb_n, 256>>>(n);
    k_scan<<<1, 1024>>>(n);
    k_scatter<<<nb_e, 256>>>(e);

    dim3 gblk(64, 8);

    // --- layer 1 ---
    k_gemm<IN_DIM><<<nb_w8, gblk>>>(x, W1, t, n);
    k_agg<<<nb_w8, 256>>>(t, b1, h, n);
    // --- layer 2 ---
    k_gemm<HID><<<nb_w8, gblk>>>(h, W2, t, n);
    k_agg<<<nb_w8, 256>>>(t, b2, h, n);
    // --- layer 3 ---
    k_gemm<HID><<<nb_w8, gblk>>>(h, W3, t, n);
    k_agg<<<nb_w8, 256>>>(t, b3, h, n);
    // --- MLP head ---
    k_mlp<<<nb_w8, 256>>>(h, Wp1, bp1, Wp2, bp2, out, n);
}

// round 2
// speedup vs baseline: 1.2138x; 1.2138x over previous
#include <cuda_runtime.h>
#include <cuda_bf16.h>

#define MAX_N   100000
#define MAX_E   1600000
#define IN_DIM  128
#define HID     64

// ---------------- device scratch ----------------
__device__ float g_t[MAX_N * HID];        // GEMM output, pre-scaled by dinv[row]
__device__ float g_h[MAX_N * HID];        // aggregated + relu activations
__device__ float g_dinv[MAX_N];           // deg^{-1/2} (incl self loop)
__device__ int   g_deg[MAX_N];            // edge-only in-degree (no self loop)
__device__ int   g_rowstart[MAX_N];       // CSR segment starts (unordered layout)
__device__ int   g_fill[MAX_N];           // scatter cursors
__device__ int   g_col[MAX_E];            // CSR column (src), grouped by dst
__device__ int   g_total;                 // segment allocator
__device__ int   g_is64;                  // edge_index dtype flag

// ---------------- dtype detection ----------------
__global__ void k_detect(const void* ei, int e, int n) {
    __shared__ int bad;
    if (threadIdx.x == 0) bad = 0;
    __syncthreads();
    const long long* p = (const long long*)ei;
    int samples = e < 2048 ? e : 2048;
    long long stride = e / samples; if (stride < 1) stride = 1;
    for (int i = threadIdx.x; i < samples; i += blockDim.x) {
        long long idx = (long long)i * stride;
        if (idx < e) {
            long long v = p[idx];
            if (v < 0 || v >= n) bad = 1;
        }
    }
    __syncthreads();
    if (threadIdx.x == 0) g_is64 = bad ? 0 : 1;
}

// ---------------- degree count (fused with dtype dispatch) ----------------
// g_deg must be zeroed beforehand (memsetAsync).
__global__ void k_count(const void* ei, int e) {
    int i = blockIdx.x * blockDim.x + threadIdx.x;
    if (i >= e) return;
    int d;
    if (g_is64) d = (int)((const long long*)ei)[e + i];
    else        d = ((const int*)ei)[e + i];
    atomicAdd(&g_deg[d], 1);
}

// ---------------- segment assignment + dinv ----------------
// CSR segments need not be ordered by node id; grab space atomically.
__global__ void k_rows(int n) {
    int i = blockIdx.x * blockDim.x + threadIdx.x;
    if (i >= n) return;
    int d = g_deg[i];
    g_dinv[i] = rsqrtf((float)(d + 1));    // +1 self loop
    int start = atomicAdd(&g_total, d);
    g_rowstart[i] = start;
    g_fill[i] = start;
}

// ---------------- scatter edges into CSR ----------------
__global__ void k_scatter(const void* ei, int e) {
    int i = blockIdx.x * blockDim.x + threadIdx.x;
    if (i >= e) return;
    int s, d;
    if (g_is64) {
        const long long* p = (const long long*)ei;
        s = (int)p[i]; d = (int)p[e + i];
    } else {
        const int* p = (const int*)ei;
        s = p[i]; d = p[e + i];
    }
    int pos = atomicAdd(&g_fill[d], 1);
    g_col[pos] = s;
}

// ---------------- dense transform with dinv epilogue --------------------
// out[r,:] = (A[r,:] @ W) * dinv[r]
template <int K>
__global__ void k_gemm(const float* __restrict__ A, const float* __restrict__ W,
                       float* __restrict__ out, int n) {
    __shared__ float Ws[K * 64];
    __shared__ float As[8 * K];
    int tx = threadIdx.x;           // 0..63 output column
    int ty = threadIdx.y;           // 0..7 row in tile
    int tid = ty * 64 + tx;
    for (int i = tid; i < K * 64; i += 512) Ws[i] = W[i];
    int row0 = blockIdx.x * 8;
    for (int i = tid; i < 8 * K; i += 512) {
        int r = row0 + i / K;
        As[i] = (r < n) ? A[(long long)r * K + (i % K)] : 0.f;
    }
    __syncthreads();
    float acc = 0.f;
    #pragma unroll
    for (int k = 0; k < K; ++k)
        acc = fmaf(As[ty * K + k], Ws[k * 64 + tx], acc);
    int row = row0 + ty;
    if (row < n) out[(long long)row * 64 + tx] = acc * g_dinv[row];
}

// ---------------- CSR aggregation: warp per node ----------------
// h[i] = relu( b + dinv_i * ( t'[i] + sum_{s in in(i)} t'[s] ) )
__global__ void k_agg(const float* __restrict__ t, const float* __restrict__ b,
                      float* __restrict__ hout, int n) {
    int warp = (blockIdx.x * blockDim.x + threadIdx.x) >> 5;
    int lane = threadIdx.x & 31;
    if (warp >= n) return;
    int i = warp;
    const float2* __restrict__ t2 = (const float2*)t;
    float2 self = t2[(long long)i * 32 + lane];
    float ax = self.x, ay = self.y;
    int s0 = g_rowstart[i];
    int s1 = s0 + g_deg[i];
    int idx = s0;
    // unroll 4: batch index loads then 4 independent gathers (MLP=4+ per warp)
    for (; idx + 3 < s1; idx += 4) {
        int c0 = g_col[idx], c1 = g_col[idx + 1];
        int c2 = g_col[idx + 2], c3 = g_col[idx + 3];
        float2 v0 = t2[(long long)c0 * 32 + lane];
        float2 v1 = t2[(long long)c1 * 32 + lane];
        float2 v2 = t2[(long long)c2 * 32 + lane];
        float2 v3 = t2[(long long)c3 * 32 + lane];
        ax += (v0.x + v1.x) + (v2.x + v3.x);
        ay += (v0.y + v1.y) + (v2.y + v3.y);
    }
    for (; idx < s1; ++idx) {
        int c = g_col[idx];
        float2 v = t2[(long long)c * 32 + lane];
        ax += v.x; ay += v.y;
    }
    float di = g_dinv[i];
    float2 o;
    o.x = fmaxf(fmaf(di, ax, b[2 * lane]), 0.f);
    o.y = fmaxf(fmaf(di, ay, b[2 * lane + 1]), 0.f);
    ((float2*)hout)[(long long)i * 32 + lane] = o;
}

// ---------------- MLP head: warp per node ----------------
__global__ void k_mlp(const float* __restrict__ h,
                      const float* __restrict__ Wp1, const float* __restrict__ bp1,
                      const float* __restrict__ Wp2, const float* __restrict__ bp2,
                      float* __restrict__ out, int n) {
    __shared__ float W1s[64 * 32];
    __shared__ float W2s[32];
    int tid = threadIdx.x;  // 256
    for (int i = tid; i < 64 * 32; i += 256) W1s[i] = Wp1[i];
    if (tid < 32) W2s[tid] = Wp2[tid];
    __syncthreads();
    int warp = tid >> 5, lane = tid & 31;
    int node = blockIdx.x * 8 + warp;
    if (node >= n) return;
    float hlo = h[(long long)node * 64 + lane];
    float hhi = h[(long long)node * 64 + 32 + lane];
    float acc = 0.f;
    #pragma unroll
    for (int k = 0; k < 32; ++k)
        acc = fmaf(__shfl_sync(0xffffffffu, hlo, k), W1s[k * 32 + lane], acc);
    #pragma unroll
    for (int k = 0; k < 32; ++k)
        acc = fmaf(__shfl_sync(0xffffffffu, hhi, k), W1s[(k + 32) * 32 + lane], acc);
    float z = fmaxf(acc + bp1[lane], 0.f);
    float p = z * W2s[lane];
    #pragma unroll
    for (int o = 16; o > 0; o >>= 1) p += __shfl_xor_sync(0xffffffffu, p, o);
    if (lane == 0) out[node] = p + bp2[0];
}

// ---------------- launch ----------------
extern "C" void kernel_launch(void* const* d_in, const int* in_sizes, int n_in,
                              void* d_out, int out_size) {
    const float* x   = (const float*)d_in[0];
    const void*  ei  = d_in[1];
    const float* W1  = (const float*)d_in[3];
    const float* b1  = (const float*)d_in[4];
    const float* W2  = (const float*)d_in[5];
    const float* b2  = (const float*)d_in[6];
    const float* W3  = (const float*)d_in[7];
    const float* b3  = (const float*)d_in[8];
    const float* Wp1 = (const float*)d_in[9];
    const float* bp1 = (const float*)d_in[10];
    const float* Wp2 = (const float*)d_in[11];
    const float* bp2 = (const float*)d_in[12];
    float* out = (float*)d_out;

    int n = in_sizes[0] / IN_DIM;
    int e = in_sizes[1] / 2;

    float* t = nullptr; float* h = nullptr;
    void* degp = nullptr; void* totp = nullptr;
    cudaGetSymbolAddress((void**)&t, g_t);
    cudaGetSymbolAddress((void**)&h, g_h);
    cudaGetSymbolAddress(&degp, g_deg);
    cudaGetSymbolAddress(&totp, g_total);

    int nb_n  = (n + 255) / 256;
    int nb_e  = (e + 255) / 256;
    int nb_w8 = (n + 7) / 8;

    // --- preprocessing ---
    cudaMemsetAsync(degp, 0, (size_t)n * sizeof(int), 0);
    cudaMemsetAsync(totp, 0, sizeof(int), 0);
    k_detect<<<1, 256>>>(ei, e, n);
    k_count<<<nb_e, 256>>>(ei, e);
    k_rows<<<nb_n, 256>>>(n);
    k_scatter<<<nb_e, 256>>>(ei, e);

    dim3 gblk(64, 8);

    // --- layer 1 ---
    k_gemm<IN_DIM><<<nb_w8, gblk>>>(x, W1, t, n);
    k_agg<<<nb_w8, 256>>>(t, b1, h, n);
    // --- layer 2 ---
    k_gemm<HID><<<nb_w8, gblk>>>(h, W2, t, n);
    k_agg<<<nb_w8, 256>>>(t, b2, h, n);
    // --- layer 3 ---
    k_gemm<HID><<<nb_w8, gblk>>>(h, W3, t, n);
    k_agg<<<nb_w8, 256>>>(t, b3, h, n);
    // --- MLP head ---
    k_mlp<<<nb_w8, 256>>>(h, Wp1, bp1, Wp2, bp2, out, n);
}

// round 3
// speedup vs baseline: 2.1864x; 1.8013x over previous
#include <cuda_runtime.h>
#include <cuda_bf16.h>

#define MAX_N   100000
#define MAX_E   1600000
#define IN_DIM  128
#define HID     64

// ---------------- device scratch ----------------
__device__ float g_t[MAX_N * HID];        // GEMM output, pre-scaled by dinv[row]
__device__ float g_h[MAX_N * HID];        // aggregated + relu activations
__device__ float g_dinv[MAX_N];           // deg^{-1/2} (incl self loop)
__device__ int   g_deg[MAX_N];            // edge-only in-degree
__device__ int   g_rowstart[MAX_N];       // CSR segment starts (unordered layout)
__device__ int   g_fill[MAX_N];           // scatter cursors
__device__ int   g_col[MAX_E];            // CSR column (src), grouped by dst
__device__ int   g_total;                 // segment allocator
__device__ int   g_is64;                  // edge_index dtype flag

// ---------------- f32x2 helpers (sm_103a packed fp32) ----------------
__device__ __forceinline__ unsigned long long fma2(unsigned long long a,
                                                   unsigned long long b,
                                                   unsigned long long c) {
    unsigned long long d;
    asm("fma.rn.f32x2 %0,%1,%2,%3;" : "=l"(d) : "l"(a), "l"(b), "l"(c));
    return d;
}
__device__ __forceinline__ unsigned long long add2(unsigned long long a,
                                                   unsigned long long b) {
    unsigned long long d;
    asm("add.rn.f32x2 %0,%1,%2;" : "=l"(d) : "l"(a), "l"(b));
    return d;
}
__device__ __forceinline__ unsigned long long pack2(float x, float y) {
    unsigned long long d;
    asm("mov.b64 %0,{%1,%2};" : "=l"(d) : "f"(x), "f"(y));
    return d;
}
__device__ __forceinline__ float2 unpack2(unsigned long long v) {
    float2 r;
    asm("mov.b64 {%0,%1},%2;" : "=f"(r.x), "=f"(r.y) : "l"(v));
    return r;
}

// ---------------- dtype detection ----------------
__global__ void k_detect(const void* ei, int e, int n) {
    __shared__ int bad;
    if (threadIdx.x == 0) bad = 0;
    __syncthreads();
    const long long* p = (const long long*)ei;
    int samples = e < 2048 ? e : 2048;
    long long stride = e / samples; if (stride < 1) stride = 1;
    for (int i = threadIdx.x; i < samples; i += blockDim.x) {
        long long idx = (long long)i * stride;
        if (idx < e) {
            long long v = p[idx];
            if (v < 0 || v >= n) bad = 1;
        }
    }
    __syncthreads();
    if (threadIdx.x == 0) g_is64 = bad ? 0 : 1;
}

// ---------------- degree count ----------------
__global__ void k_count(const void* ei, int e) {
    int i = blockIdx.x * blockDim.x + threadIdx.x;
    if (i >= e) return;
    int d;
    if (g_is64) d = (int)((const long long*)ei)[e + i];
    else        d = ((const int*)ei)[e + i];
    atomicAdd(&g_deg[d], 1);
}

// ---------------- segment assignment + dinv ----------------
__global__ void k_rows(int n) {
    int i = blockIdx.x * blockDim.x + threadIdx.x;
    if (i >= n) return;
    int d = g_deg[i];
    g_dinv[i] = rsqrtf((float)(d + 1));
    int start = atomicAdd(&g_total, d);
    g_rowstart[i] = start;
    g_fill[i] = start;
}

// ---------------- scatter edges into CSR ----------------
__global__ void k_scatter(const void* ei, int e) {
    int i = blockIdx.x * blockDim.x + threadIdx.x;
    if (i >= e) return;
    int s, d;
    if (g_is64) {
        const long long* p = (const long long*)ei;
        s = (int)p[i]; d = (int)p[e + i];
    } else {
        const int* p = (const int*)ei;
        s = p[i]; d = p[e + i];
    }
    int pos = atomicAdd(&g_fill[d], 1);
    g_col[pos] = s;
}

// ---------------- register-blocked GEMM with f32x2 ----------------
// out[r,:] = (A[r,:K] @ W[K,64]) * dinv[r]
// Block: 256 threads (8 warps). Tile: 128 rows x 64 cols.
// Warp w owns rows w*16..w*16+15; lane owns col pair (2*lane, 2*lane+1).
template <int K>
__global__ __launch_bounds__(256) void k_gemm(const float* __restrict__ A,
                                              const float* __restrict__ W,
                                              float* __restrict__ out, int n) {
    __shared__ float As[128 * 64];   // 32 KB (rows x k-chunk)
    __shared__ float Ws[64 * 64];    // 16 KB (k x col)
    int tid = threadIdx.x;
    int lane = tid & 31;
    int w = tid >> 5;
    int row0 = blockIdx.x * 128;

    unsigned long long acc[16];
    #pragma unroll
    for (int j = 0; j < 16; ++j) acc[j] = 0ull;

    #pragma unroll
    for (int kc = 0; kc < K; kc += 64) {
        // load W chunk [64 k x 64 c]
        {
            const float4* Wg = (const float4*)(W + kc * 64);
            float4* Wsv = (float4*)Ws;
            #pragma unroll
            for (int i = 0; i < 4; ++i)
                Wsv[tid + i * 256] = Wg[tid + i * 256];
        }
        // load A tile [128 rows x 64 k]
        {
            float4* Asv = (float4*)As;
            #pragma unroll
            for (int i = 0; i < 8; ++i) {
                int f = tid + i * 256;          // float4 slot, 2048 total
                int r = f >> 4;                 // 16 float4 per row
                int kk = (f & 15) * 4;
                int gr = row0 + r;
                float4 v = make_float4(0.f, 0.f, 0.f, 0.f);
                if (gr < n) v = *(const float4*)(A + (size_t)gr * K + kc + kk);
                Asv[f] = v;
            }
        }
        __syncthreads();
        #pragma unroll 4
        for (int k = 0; k < 64; ++k) {
            unsigned long long w2 = *(const unsigned long long*)&Ws[k * 64 + 2 * lane];
            #pragma unroll
            for (int j = 0; j < 16; ++j) {
                float a = As[(w * 16 + j) * 64 + k];
                acc[j] = fma2(pack2(a, a), w2, acc[j]);
            }
        }
        __syncthreads();
    }
    #pragma unroll
    for (int j = 0; j < 16; ++j) {
        int r = row0 + w * 16 + j;
        if (r < n) {
            float di = g_dinv[r];
            float2 v = unpack2(acc[j]);
            float2 o; o.x = v.x * di; o.y = v.y * di;
            ((float2*)out)[(size_t)r * 32 + lane] = o;
        }
    }
}

// ---------------- CSR aggregation: persistent, warp per node ----------------
// h[i] = relu( b + dinv_i * ( t'[i] + sum_{s in in(i)} t'[s] ) )
__global__ __launch_bounds__(256) void k_agg(const float* __restrict__ t,
                                             const float* __restrict__ b,
                                             float* __restrict__ hout, int n) {
    int tid = threadIdx.x;
    int lane = tid & 31;
    int gw = (blockIdx.x * 256 + tid) >> 5;
    int nw = (gridDim.x * 256) >> 5;
    const unsigned long long* __restrict__ t8 = (const unsigned long long*)t;
    float bx = b[2 * lane], by = b[2 * lane + 1];
    for (int i = gw; i < n; i += nw) {
        unsigned long long acc0 = t8[(size_t)i * 32 + lane];  // self term
        unsigned long long acc1 = 0ull;
        int s0 = g_rowstart[i];
        int s1 = s0 + g_deg[i];
        int idx = s0;
        for (; idx + 3 < s1; idx += 4) {
            int c0 = g_col[idx],     c1 = g_col[idx + 1];
            int c2 = g_col[idx + 2], c3 = g_col[idx + 3];
            unsigned long long v0 = t8[(size_t)c0 * 32 + lane];
            unsigned long long v1 = t8[(size_t)c1 * 32 + lane];
            unsigned long long v2 = t8[(size_t)c2 * 32 + lane];
            unsigned long long v3 = t8[(size_t)c3 * 32 + lane];
            acc0 = add2(acc0, v0);
            acc1 = add2(acc1, v1);
            acc0 = add2(acc0, v2);
            acc1 = add2(acc1, v3);
        }
        for (; idx < s1; ++idx) {
            int c = g_col[idx];
            acc0 = add2(acc0, t8[(size_t)c * 32 + lane]);
        }
        float2 s = unpack2(add2(acc0, acc1));
        float di = g_dinv[i];
        float2 o;
        o.x = fmaxf(fmaf(di, s.x, bx), 0.f);
        o.y = fmaxf(fmaf(di, s.y, by), 0.f);
        ((float2*)hout)[(size_t)i * 32 + lane] = o;
    }
}

// ---------------- MLP head: persistent, warp per node ----------------
__global__ __launch_bounds__(256) void k_mlp(const float* __restrict__ h,
                                             const float* __restrict__ Wp1,
                                             const float* __restrict__ bp1,
                                             const float* __restrict__ Wp2,
                                             const float* __restrict__ bp2,
                                             float* __restrict__ out, int n) {
    __shared__ float W1s[64 * 32];
    __shared__ float W2s[32];
    int tid = threadIdx.x;
    for (int i = tid; i < 64 * 32; i += 256) W1s[i] = Wp1[i];
    if (tid < 32) W2s[tid] = Wp2[tid];
    __syncthreads();
    int lane = tid & 31;
    int gw = (blockIdx.x * 256 + tid) >> 5;
    int nw = (gridDim.x * 256) >> 5;
    float bb = bp1[lane];
    float w2v = W2s[lane];
    float b2v = bp2[0];
    for (int node = gw; node < n; node += nw) {
        float hlo = h[(size_t)node * 64 + lane];
        float hhi = h[(size_t)node * 64 + 32 + lane];
        float acc = 0.f;
        #pragma unroll
        for (int k = 0; k < 32; ++k)
            acc = fmaf(__shfl_sync(0xffffffffu, hlo, k), W1s[k * 32 + lane], acc);
        #pragma unroll
        for (int k = 0; k < 32; ++k)
            acc = fmaf(__shfl_sync(0xffffffffu, hhi, k), W1s[(k + 32) * 32 + lane], acc);
        float z = fmaxf(acc + bb, 0.f);
        float p = z * w2v;
        #pragma unroll
        for (int o = 16; o > 0; o >>= 1) p += __shfl_xor_sync(0xffffffffu, p, o);
        if (lane == 0) out[node] = p + b2v;
    }
}

// ---------------- launch ----------------
extern "C" void kernel_launch(void* const* d_in, const int* in_sizes, int n_in,
                              void* d_out, int out_size) {
    const float* x   = (const float*)d_in[0];
    const void*  ei  = d_in[1];
    const float* W1  = (const float*)d_in[3];
    const float* b1  = (const float*)d_in[4];
    const float* W2  = (const float*)d_in[5];
    const float* b2  = (const float*)d_in[6];
    const float* W3  = (const float*)d_in[7];
    const float* b3  = (const float*)d_in[8];
    const float* Wp1 = (const float*)d_in[9];
    const float* bp1 = (const float*)d_in[10];
    const float* Wp2 = (const float*)d_in[11];
    const float* bp2 = (const float*)d_in[12];
    float* out = (float*)d_out;

    int n = in_sizes[0] / IN_DIM;
    int e = in_sizes[1] / 2;

    float* t = nullptr; float* h = nullptr;
    void* degp = nullptr; void* totp = nullptr;
    cudaGetSymbolAddress((void**)&t, g_t);
    cudaGetSymbolAddress((void**)&h, g_h);
    cudaGetSymbolAddress(&degp, g_deg);
    cudaGetSymbolAddress(&totp, g_total);

    int nb_n = (n + 255) / 256;
    int nb_e = (e + 255) / 256;
    int nb_g = (n + 127) / 128;      // gemm tiles
    int nb_p = 592;                  // persistent grids (148 SMs x 4)

    // --- preprocessing ---
    cudaMemsetAsync(degp, 0, (size_t)n * sizeof(int), 0);
    cudaMemsetAsync(totp, 0, sizeof(int), 0);
    k_detect<<<1, 256>>>(ei, e, n);
    k_count<<<nb_e, 256>>>(ei, e);
    k_rows<<<nb_n, 256>>>(n);
    k_scatter<<<nb_e, 256>>>(ei, e);

    // --- layer 1 ---
    k_gemm<IN_DIM><<<nb_g, 256>>>(x, W1, t, n);
    k_agg<<<nb_p, 256>>>(t, b1, h, n);
    // --- layer 2 ---
    k_gemm<HID><<<nb_g, 256>>>(h, W2, t, n);
    k_agg<<<nb_p, 256>>>(t, b2, h, n);
    // --- layer 3 ---
    k_gemm<HID><<<nb_g, 256>>>(h, W3, t, n);
    k_agg<<<nb_p, 256>>>(t, b3, h, n);
    // --- MLP head ---
    k_mlp<<<nb_p, 256>>>(h, Wp1, bp1, Wp2, bp2, out, n);
}